// round 15
// baseline (speedup 1.0000x reference)
#include <cuda_runtime.h>
#include <cuda_bf16.h>

// SpatialTransformer: out[n,c,h,w] = bilinear(src[n,c], x=w+flow[n,0,h,w], y=h+flow[n,1,h,w])
// with zero outside [0,W-1]x[0,H-1] (reference's zero-pad + clamp is equivalent to
// zeroing the weight of any out-of-range corner).
//
// N=4, C=32, H=W=512, fp32. One thread per (n,h,w) pixel, loops all 32 channels:
// sampling indices/weights computed once, 4 unconditional gathers + 1 coalesced
// store per channel. Blocks are 32x8 spatial tiles for L1 gather locality.

#define N_ 4
#define C_ 32
#define H_ 512
#define W_ 512

__global__ __launch_bounds__(256, 6)
void st_warp_kernel(const float* __restrict__ src,
                    const float* __restrict__ flow,
                    float* __restrict__ out)
{
    const int tx = threadIdx.x & 31;
    const int ty = threadIdx.x >> 5;
    const int w = (blockIdx.x << 5) + tx;      // 32-wide -> coalesced stores
    const int h = (blockIdx.y << 3) + ty;      // 8 rows per block
    const int n = blockIdx.z;

    const int HW  = H_ * W_;
    const int pix = h * W_ + w;

    // flow layout (N, 2, H, W)
    const float dx = flow[(size_t)n * 2 * HW + pix];
    const float dy = flow[(size_t)n * 2 * HW + HW + pix];

    // normalize->unnormalize round-trip in the reference is the identity
    const float x = (float)w + dx;
    const float y = (float)h + dy;

    const float x0f = floorf(x);
    const float y0f = floorf(y);
    const int ix0 = (int)x0f;
    const int iy0 = (int)y0f;
    const int ix1 = ix0 + 1;
    const int iy1 = iy0 + 1;

    const float fx = x - x0f;
    const float fy = y - y0f;
    float wa = (1.0f - fx) * (1.0f - fy);   // (x0, y0)
    float wb = (1.0f - fx) * fy;            // (x0, y1)
    float wc = fx * (1.0f - fy);            // (x1, y0)
    float wd = fx * fy;                     // (x1, y1)

    // validity of each corner; invalid corner contributes exactly 0
    const bool vx0 = (unsigned)ix0 < (unsigned)W_;
    const bool vx1 = (unsigned)ix1 < (unsigned)W_;
    const bool vy0 = (unsigned)iy0 < (unsigned)H_;
    const bool vy1 = (unsigned)iy1 < (unsigned)H_;
    if (!(vx0 && vy0)) wa = 0.0f;
    if (!(vx0 && vy1)) wb = 0.0f;
    if (!(vx1 && vy0)) wc = 0.0f;
    if (!(vx1 && vy1)) wd = 0.0f;

    // clamp offsets into range so gathers are always safe (weight is 0 if clamped)
    const int cx0 = min(max(ix0, 0), W_ - 1);
    const int cx1 = min(max(ix1, 0), W_ - 1);
    const int cy0 = min(max(iy0, 0), H_ - 1);
    const int cy1 = min(max(iy1, 0), H_ - 1);

    const int o00 = cy0 * W_ + cx0;
    const int o01 = cy1 * W_ + cx0;
    const int o10 = cy0 * W_ + cx1;
    const int o11 = cy1 * W_ + cx1;

    const float* __restrict__ p = src + (size_t)n * C_ * HW;
    float* __restrict__       q = out + (size_t)n * C_ * HW + pix;

    #pragma unroll 4
    for (int c = 0; c < C_; ++c) {
        const float* pc = p + c * HW;
        const float Ia = __ldg(pc + o00);
        const float Ib = __ldg(pc + o01);
        const float Ic = __ldg(pc + o10);
        const float Id = __ldg(pc + o11);
        q[(size_t)c * HW] = wa * Ia + wb * Ib + wc * Ic + wd * Id;
    }
}

extern "C" void kernel_launch(void* const* d_in, const int* in_sizes, int n_in,
                              void* d_out, int out_size)
{
    const float* src  = (const float*)d_in[0];   // (4, 32, 512, 512)
    const float* flow = (const float*)d_in[1];   // (4, 2, 512, 512)
    float* out = (float*)d_out;                  // (4, 32, 512, 512)

    dim3 block(256, 1, 1);
    dim3 grid(W_ / 32, H_ / 8, N_);
    st_warp_kernel<<<grid, block>>>(src, flow, out);
}

// round 16
// speedup vs baseline: 1.0063x; 1.0063x over previous
#include <cuda_runtime.h>
#include <cuda_bf16.h>

// SpatialTransformer: out[n,c,h,w] = bilinear(src[n,c], x=w+flow[n,0,h,w], y=h+flow[n,1,h,w])
// with zero outside [0,W-1]x[0,H-1] (reference's zero-pad + clamp is equivalent to
// zeroing the weight of any out-of-range corner).
//
// N=4, C=32, H=W=512, fp32. One thread per (n,h,w) pixel, loops all 32 channels:
// sampling indices/weights computed once, 4 unconditional gathers + 1 coalesced
// store per channel. Blocks are 32x8 spatial tiles for L1 gather locality.

#define N_ 4
#define C_ 32
#define H_ 512
#define W_ 512

__global__ __launch_bounds__(256, 6)
void st_warp_kernel(const float* __restrict__ src,
                    const float* __restrict__ flow,
                    float* __restrict__ out)
{
    const int tx = threadIdx.x & 31;
    const int ty = threadIdx.x >> 5;
    const int w = (blockIdx.x << 5) + tx;      // 32-wide -> coalesced stores
    const int h = (blockIdx.y << 3) + ty;      // 8 rows per block
    const int n = blockIdx.z;

    const int HW  = H_ * W_;
    const int pix = h * W_ + w;

    // flow layout (N, 2, H, W)
    const float dx = flow[(size_t)n * 2 * HW + pix];
    const float dy = flow[(size_t)n * 2 * HW + HW + pix];

    // normalize->unnormalize round-trip in the reference is the identity
    const float x = (float)w + dx;
    const float y = (float)h + dy;

    const float x0f = floorf(x);
    const float y0f = floorf(y);
    const int ix0 = (int)x0f;
    const int iy0 = (int)y0f;
    const int ix1 = ix0 + 1;
    const int iy1 = iy0 + 1;

    const float fx = x - x0f;
    const float fy = y - y0f;
    float wa = (1.0f - fx) * (1.0f - fy);   // (x0, y0)
    float wb = (1.0f - fx) * fy;            // (x0, y1)
    float wc = fx * (1.0f - fy);            // (x1, y0)
    float wd = fx * fy;                     // (x1, y1)

    // validity of each corner; invalid corner contributes exactly 0
    const bool vx0 = (unsigned)ix0 < (unsigned)W_;
    const bool vx1 = (unsigned)ix1 < (unsigned)W_;
    const bool vy0 = (unsigned)iy0 < (unsigned)H_;
    const bool vy1 = (unsigned)iy1 < (unsigned)H_;
    if (!(vx0 && vy0)) wa = 0.0f;
    if (!(vx0 && vy1)) wb = 0.0f;
    if (!(vx1 && vy0)) wc = 0.0f;
    if (!(vx1 && vy1)) wd = 0.0f;

    // clamp offsets into range so gathers are always safe (weight is 0 if clamped)
    const int cx0 = min(max(ix0, 0), W_ - 1);
    const int cx1 = min(max(ix1, 0), W_ - 1);
    const int cy0 = min(max(iy0, 0), H_ - 1);
    const int cy1 = min(max(iy1, 0), H_ - 1);

    const int o00 = cy0 * W_ + cx0;
    const int o01 = cy1 * W_ + cx0;
    const int o10 = cy0 * W_ + cx1;
    const int o11 = cy1 * W_ + cx1;

    const float* __restrict__ p = src + (size_t)n * C_ * HW;
    float* __restrict__       q = out + (size_t)n * C_ * HW + pix;

    #pragma unroll 4
    for (int c = 0; c < C_; ++c) {
        const float* pc = p + c * HW;
        const float Ia = __ldg(pc + o00);
        const float Ib = __ldg(pc + o01);
        const float Ic = __ldg(pc + o10);
        const float Id = __ldg(pc + o11);
        q[(size_t)c * HW] = wa * Ia + wb * Ib + wc * Ic + wd * Id;
    }
}

extern "C" void kernel_launch(void* const* d_in, const int* in_sizes, int n_in,
                              void* d_out, int out_size)
{
    const float* src  = (const float*)d_in[0];   // (4, 32, 512, 512)
    const float* flow = (const float*)d_in[1];   // (4, 2, 512, 512)
    float* out = (float*)d_out;                  // (4, 32, 512, 512)

    dim3 block(256, 1, 1);
    dim3 grid(W_ / 32, H_ / 8, N_);
    st_warp_kernel<<<grid, block>>>(src, flow, out);
}